// round 11
// baseline (speedup 1.0000x reference)
#include <cuda_runtime.h>
#include <cuda_fp16.h>
#include <cstdint>

#define BB 4
#define CH 1024
#define HH 50
#define WW 50
#define KK 512
#define NPIX (HH*WW)              // 2500
#define GPTS 8

// NHWC-transposed features in fp16: [B][H][W][C]  (20.5 MB scratch)
__device__ __align__(16) __half FT[BB * HH * WW * CH];

__device__ __forceinline__ uint32_t smem_u32(const void* p) {
    uint32_t a;
    asm("{ .reg .u64 t; cvta.to.shared.u64 t, %1; cvt.u32.u64 %0, t; }"
        : "=r"(a) : "l"(p));
    return a;
}
#define CP_ASYNC16(s, g) \
    asm volatile("cp.async.ca.shared.global [%0], [%1], 16;" :: "r"(s), "l"(g))
template<int N> __device__ __forceinline__ void cp_wait() {
    asm volatile("cp.async.wait_group %0;" :: "n"(N));
}
__device__ __forceinline__ void cp_commit() {
    asm volatile("cp.async.commit_group;");
}

// ---------------------------------------------------------------------------
// Kernel 1: NCHW fp32 -> NHWC fp16 transpose-convert (measured ~12us)
// ---------------------------------------------------------------------------
__global__ __launch_bounds__(256)
void transpose_kernel(const float* __restrict__ f) {
    __shared__ __align__(16) float tile[32][133];
    const int b  = blockIdx.z;
    const int p0 = blockIdx.x * 128;
    const int c0 = blockIdx.y * 32;
    const int t  = threadIdx.x;

    const float* fb = f + (size_t)b * CH * NPIX + (size_t)c0 * NPIX;
    #pragma unroll
    for (int j = 0; j < 4; j++) {
        int idx = t + j * 256;
        int c = idx >> 5;
        int q = idx & 31;
        int p = p0 + 4 * q;
        float4 v = make_float4(0.f, 0.f, 0.f, 0.f);
        if (p < NPIX) v = *(const float4*)(fb + (size_t)c * NPIX + p);
        tile[c][4 * q + 0] = v.x;
        tile[c][4 * q + 1] = v.y;
        tile[c][4 * q + 2] = v.z;
        tile[c][4 * q + 3] = v.w;
    }
    __syncthreads();

    __half* ob = FT + (size_t)b * NPIX * CH + c0;
    #pragma unroll
    for (int j = 0; j < 2; j++) {
        int idx = t + j * 256;
        int p = idx >> 2;
        int g = idx & 3;
        if (p0 + p < NPIX) {
            __half2 h0 = __floats2half2_rn(tile[8*g + 0][p], tile[8*g + 1][p]);
            __half2 h1 = __floats2half2_rn(tile[8*g + 2][p], tile[8*g + 3][p]);
            __half2 h2 = __floats2half2_rn(tile[8*g + 4][p], tile[8*g + 5][p]);
            __half2 h3 = __floats2half2_rn(tile[8*g + 6][p], tile[8*g + 7][p]);
            uint4 v;
            v.x = *(const unsigned int*)&h0;
            v.y = *(const unsigned int*)&h1;
            v.z = *(const unsigned int*)&h2;
            v.w = *(const unsigned int*)&h3;
            *(uint4*)(ob + (size_t)(p0 + p) * CH + 8 * g) = v;
        }
    }
}

// ---------------------------------------------------------------------------
// Kernel 2: fused RoIAlign + 2x2 avg pool, cp.async taps + pooled-row split.
// Grid (K, 2, 2): channel half x row flavor.
//   z=0: pooled rows 0-3, grid rows 0-4 (acc 28xfloat2 = 56 regs)
//   z=1: pooled rows 4-6, grid rows 4-7 (acc 21xfloat2 = 42 regs)
// 256 threads, 2 ch/thread; 85-reg cap -> 3 CTAs/SM (24 warps).
// Taps double-buffered in 2x32KB dynamic smem; staging aliases buffer 0.
// ---------------------------------------------------------------------------
#define TB_BYTES 32768            // one tap buffer: 32 segs x 1KB

extern __shared__ __align__(16) unsigned char dynsmem[];   // 2*TB_BYTES

template<int GY0, int NPR>        // NPR pooled rows from grid rows GY0..GY0+NPR
__device__ __forceinline__
void roi_body(float* __restrict__ out, int k, int chunk, int tid,
              const float (*s_w)[GPTS][4], const int* s_x0, const int* s_y0,
              int s_b) {
    constexpr int PXW = NPR * 7;
    constexpr int SST = PXW + 1;  // padded smem stride for staging

    // gather role: t4 = tap, col = 16B chunk within 1KB segment
    const int t4  = tid >> 6;
    const int dy  = t4 >> 1, dx = t4 & 1;
    const int col = tid & 63;
    const __half* bbase = FT + (size_t)s_b * (NPIX * CH) + chunk * 512
                             + (size_t)dx * CH + col * 8;
    int xoff[GPTS];
    #pragma unroll
    for (int gx = 0; gx < GPTS; gx++) xoff[gx] = s_x0[gx] * CH;

    const uint32_t tb0 = smem_u32(dynsmem);
    const uint32_t smy = tb0 + (t4 * 1024 + col * 16);

    #define GATHER(gy, bi)                                                  \
        do {                                                                \
            const __half* rb = bbase + (size_t)(s_y0[gy] + dy) * (WW * CH); \
            uint32_t sb = smy + (bi) * TB_BYTES;                            \
            _Pragma("unroll")                                               \
            for (int j = 0; j < 8; j++)                                     \
                CP_ASYNC16(sb + j * 4096, rb + xoff[j]);                    \
            cp_commit();                                                    \
        } while (0)

    GATHER(GY0, 0);                        // prologue

    float2 acc[PXW];
    #pragma unroll
    for (int i = 0; i < PXW; i++) { acc[i].x = 0.0f; acc[i].y = 0.0f; }

    #pragma unroll
    for (int g = 0; g <= NPR; g++) {
        const int gy = GY0 + g;
        if (g < NPR) GATHER(gy + 1, (g + 1) & 1);
        if (g < NPR) cp_wait<1>(); else cp_wait<0>();
        __syncthreads();

        const unsigned char* buf = dynsmem + (g & 1) * TB_BYTES;
        #pragma unroll
        for (int gx = 0; gx < GPTS; gx++) {
            const float4 w = *(const float4*)&s_w[gy][gx][0];
            const unsigned char* sp = buf + (gx * 4) * 1024 + tid * 4;
            float2 f00 = __half22float2(*(const __half2*)(sp));
            float2 f01 = __half22float2(*(const __half2*)(sp + 1024));
            float2 f10 = __half22float2(*(const __half2*)(sp + 2048));
            float2 f11 = __half22float2(*(const __half2*)(sp + 3072));

            float ax = f00.x*w.x + f01.x*w.y + f10.x*w.z + f11.x*w.w;
            float ay = f00.y*w.x + f01.y*w.y + f10.y*w.z + f11.y*w.w;

            if (g >= 1) {
                if (gx >= 1) { acc[(g-1)*7 + (gx-1)].x += ax; acc[(g-1)*7 + (gx-1)].y += ay; }
                if (gx <  7) { acc[(g-1)*7 +  gx   ].x += ax; acc[(g-1)*7 +  gx   ].y += ay; }
            }
            if (g < NPR) {
                if (gx >= 1) { acc[ g   *7 + (gx-1)].x += ax; acc[ g   *7 + (gx-1)].y += ay; }
                if (gx <  7) { acc[ g   *7 +  gx   ].x += ax; acc[ g   *7 +  gx   ].y += ay; }
            }
        }
        __syncthreads();
    }
    #undef GATHER

    // ---- staged output writes (staging aliases gather buffer 0) --------
    // CTA owns out[k, chunk*512 .. +511, GY0*7 .. GY0*7+PXW-1].
    float* sbuf = (float*)dynsmem;         // 128*SST floats << TB_BYTES
    float* outk = out + (size_t)k * (CH * 49) + (size_t)chunk * (512 * 49)
                      + GY0 * 7;
    #pragma unroll
    for (int sub = 0; sub < 4; sub++) {
        if ((tid >> 6) == sub) {
            int cl = tid * 2 - sub * 128;  // 0..126, even
            #pragma unroll
            for (int i = 0; i < PXW; i++) {
                sbuf[(cl    ) * SST + i] = acc[i].x;
                sbuf[(cl + 1) * SST + i] = acc[i].y;
            }
        }
        __syncthreads();
        float* outc = outk + (size_t)sub * (128 * 49);
        constexpr int N = 128 * PXW;
        #pragma unroll
        for (int j = 0; j < (N + 255) / 256; j++) {
            int i = tid + j * 256;
            if (i < N) {
                int c  = i / PXW;          // compile-time magic division
                int px = i - c * PXW;
                outc[c * 49 + px] = sbuf[c * SST + px];
            }
        }
        __syncthreads();
    }
}

__global__ __launch_bounds__(256, 3)
void roi_pool_kernel(const float* __restrict__ rois, float* __restrict__ out) {
    const int k     = blockIdx.x;
    const int chunk = blockIdx.y;          // channel half
    const int z     = blockIdx.z;          // row flavor
    const int tid   = threadIdx.x;

    __shared__ __align__(16) float s_w[GPTS][GPTS][4];
    __shared__ float s_wx[GPTS], s_wy[GPTS], s_vx[GPTS], s_vy[GPTS];
    __shared__ int   s_x0[GPTS], s_y0[GPTS];
    __shared__ int   s_b;

    if (tid < GPTS) {
        float x1 = __ldg(&rois[k * 5 + 1]) * 0.0625f;
        float y1 = __ldg(&rois[k * 5 + 2]) * 0.0625f;
        float x2 = __ldg(&rois[k * 5 + 3]) * 0.0625f;
        float y2 = __ldg(&rois[k * 5 + 4]) * 0.0625f;
        float bh = fmaxf(y2 - y1, 0.0f) * (1.0f / 7.0f);
        float bw = fmaxf(x2 - x1, 0.0f) * (1.0f / 7.0f);
        float xv = x1 + (float)tid * bw;
        float yv = y1 + (float)tid * bh;
        s_vx[tid] = (xv >= 0.0f && xv < (float)WW) ? 1.0f : 0.0f;
        s_vy[tid] = (yv >= 0.0f && yv < (float)HH) ? 1.0f : 0.0f;
        int x0 = (int)floorf(xv);  x0 = min(max(x0, 0), WW - 2);
        int y0 = (int)floorf(yv);  y0 = min(max(y0, 0), HH - 2);
        s_x0[tid] = x0;  s_y0[tid] = y0;
        s_wx[tid] = xv - (float)x0;
        s_wy[tid] = yv - (float)y0;
        if (tid == 0) s_b = (int)__ldg(&rois[k * 5 + 0]);
    }
    __syncthreads();

    if (tid < 64) {
        int gy = tid >> 3, gx = tid & 7;
        float wy = s_wy[gy], wx = s_wx[gx];
        float sc = 0.25f * s_vy[gy] * s_vx[gx];
        s_w[gy][gx][0] = (1.0f - wy) * (1.0f - wx) * sc;
        s_w[gy][gx][1] = (1.0f - wy) * wx * sc;
        s_w[gy][gx][2] = wy * (1.0f - wx) * sc;
        s_w[gy][gx][3] = wy * wx * sc;
    }
    __syncthreads();

    if (z == 0) roi_body<0, 4>(out, k, chunk, tid, s_w, s_x0, s_y0, s_b);
    else        roi_body<4, 3>(out, k, chunk, tid, s_w, s_x0, s_y0, s_b);
}

// ---------------------------------------------------------------------------
extern "C" void kernel_launch(void* const* d_in, const int* in_sizes, int n_in,
                              void* d_out, int out_size) {
    const float* features = (const float*)d_in[0];
    const float* rois     = (const float*)d_in[1];
    float* out            = (float*)d_out;

    const int smem = 2 * TB_BYTES;         // 64 KB
    static int done = 0;
    if (!done) {
        cudaFuncSetAttribute(roi_pool_kernel,
                             cudaFuncAttributeMaxDynamicSharedMemorySize, smem);
        done = 1;
    }

    dim3 tgrid((NPIX + 127) / 128, CH / 32, BB);   // (20, 32, 4)
    transpose_kernel<<<tgrid, 256>>>(features);
    roi_pool_kernel<<<dim3(KK, 2, 2), 256, smem>>>(rois, out);
}

// round 12
// speedup vs baseline: 1.5976x; 1.5976x over previous
#include <cuda_runtime.h>
#include <cuda_fp16.h>
#include <cstdint>
#include <cstring>

#define BB 4
#define CH 1024
#define HH 50
#define WW 50
#define KK 512
#define NPIX (HH*WW)              // 2500
#define GPTS 8

// NHWC-transposed features in fp16: [B][H][W][C]  (20.5 MB scratch)
__device__ __align__(16) __half FT[BB * HH * WW * CH];

__device__ __forceinline__ uint32_t smem_u32(const void* p) {
    uint32_t a;
    asm("{ .reg .u64 t; cvta.to.shared.u64 t, %1; cvt.u32.u64 %0, t; }"
        : "=r"(a) : "l"(p));
    return a;
}
#define CP_ASYNC16(s, g) \
    asm volatile("cp.async.ca.shared.global [%0], [%1], 16;" :: "r"(s), "l"(g))
template<int N> __device__ __forceinline__ void cp_wait() {
    asm volatile("cp.async.wait_group %0;" :: "n"(N));
}
__device__ __forceinline__ void cp_commit() {
    asm volatile("cp.async.commit_group;");
}

// ---- packed f32x2 helpers (sm_103a FFMA2 path, fp32-exact) ---------------
typedef unsigned long long ull;
__device__ __forceinline__ ull dup2(float w) {
    ull d; asm("mov.b64 %0, {%1, %1};" : "=l"(d) : "f"(w)); return d;
}
__device__ __forceinline__ ull fmul2(ull a, ull b) {
    ull d; asm("mul.rn.f32x2 %0, %1, %2;" : "=l"(d) : "l"(a), "l"(b)); return d;
}
__device__ __forceinline__ ull ffma2(ull a, ull b, ull c) {
    ull d; asm("fma.rn.f32x2 %0, %1, %2, %3;" : "=l"(d) : "l"(a), "l"(b), "l"(c)); return d;
}
__device__ __forceinline__ ull fadd2(ull a, ull b) {
    ull d; asm("add.rn.f32x2 %0, %1, %2;" : "=l"(d) : "l"(a), "l"(b)); return d;
}
__device__ __forceinline__ ull h2f2(unsigned int h) {
    __half2 hh; memcpy(&hh, &h, 4);
    float2 f = __half22float2(hh);
    ull u; memcpy(&u, &f, 8); return u;
}

// ---------------------------------------------------------------------------
// Kernel 1: NCHW fp32 -> NHWC fp16 transpose-convert (measured ~12us)
// ---------------------------------------------------------------------------
__global__ __launch_bounds__(256)
void transpose_kernel(const float* __restrict__ f) {
    __shared__ __align__(16) float tile[32][133];
    const int b  = blockIdx.z;
    const int p0 = blockIdx.x * 128;
    const int c0 = blockIdx.y * 32;
    const int t  = threadIdx.x;

    const float* fb = f + (size_t)b * CH * NPIX + (size_t)c0 * NPIX;
    #pragma unroll
    for (int j = 0; j < 4; j++) {
        int idx = t + j * 256;
        int c = idx >> 5;
        int q = idx & 31;
        int p = p0 + 4 * q;
        float4 v = make_float4(0.f, 0.f, 0.f, 0.f);
        if (p < NPIX) v = *(const float4*)(fb + (size_t)c * NPIX + p);
        tile[c][4 * q + 0] = v.x;
        tile[c][4 * q + 1] = v.y;
        tile[c][4 * q + 2] = v.z;
        tile[c][4 * q + 3] = v.w;
    }
    __syncthreads();

    __half* ob = FT + (size_t)b * NPIX * CH + c0;
    #pragma unroll
    for (int j = 0; j < 2; j++) {
        int idx = t + j * 256;
        int p = idx >> 2;
        int g = idx & 3;
        if (p0 + p < NPIX) {
            __half2 h0 = __floats2half2_rn(tile[8*g + 0][p], tile[8*g + 1][p]);
            __half2 h1 = __floats2half2_rn(tile[8*g + 2][p], tile[8*g + 3][p]);
            __half2 h2 = __floats2half2_rn(tile[8*g + 4][p], tile[8*g + 5][p]);
            __half2 h3 = __floats2half2_rn(tile[8*g + 6][p], tile[8*g + 7][p]);
            uint4 v;
            v.x = *(const unsigned int*)&h0;
            v.y = *(const unsigned int*)&h1;
            v.z = *(const unsigned int*)&h2;
            v.w = *(const unsigned int*)&h3;
            *(uint4*)(ob + (size_t)(p0 + p) * CH + 8 * g) = v;
        }
    }
}

// ---------------------------------------------------------------------------
// Kernel 2: fused RoIAlign + 2x2 avg pool (R10 frame).
// Grid (K,2): 512 ch/CTA, 256 threads, 2 ch/thread, 8-row sweep.
// cp.async taps, TRIPLE-buffered (lookahead 2 rows), 1 sync/row.
// Packed f32x2 math + rowsum. 49xull accumulator. R10 float4 drain
// (staging aliases buffer 0).
// ---------------------------------------------------------------------------
#define TB_BYTES 32768            // one tap buffer: 32 segs x 1KB

extern __shared__ __align__(16) unsigned char dynsmem[];   // 3*TB_BYTES

__global__ __launch_bounds__(256, 2)
void roi_pool_kernel(const float* __restrict__ rois, float* __restrict__ out) {
    const int k     = blockIdx.x;
    const int chunk = blockIdx.y;          // channel half
    const int tid   = threadIdx.x;

    __shared__ __align__(16) float s_w[GPTS][GPTS][4];
    __shared__ float s_wx[GPTS], s_wy[GPTS], s_vx[GPTS], s_vy[GPTS];
    __shared__ int   s_x0[GPTS], s_y0[GPTS];
    __shared__ int   s_b;

    if (tid < GPTS) {
        float x1 = __ldg(&rois[k * 5 + 1]) * 0.0625f;
        float y1 = __ldg(&rois[k * 5 + 2]) * 0.0625f;
        float x2 = __ldg(&rois[k * 5 + 3]) * 0.0625f;
        float y2 = __ldg(&rois[k * 5 + 4]) * 0.0625f;
        float bh = fmaxf(y2 - y1, 0.0f) * (1.0f / 7.0f);
        float bw = fmaxf(x2 - x1, 0.0f) * (1.0f / 7.0f);
        float xv = x1 + (float)tid * bw;
        float yv = y1 + (float)tid * bh;
        s_vx[tid] = (xv >= 0.0f && xv < (float)WW) ? 1.0f : 0.0f;
        s_vy[tid] = (yv >= 0.0f && yv < (float)HH) ? 1.0f : 0.0f;
        int x0 = (int)floorf(xv);  x0 = min(max(x0, 0), WW - 2);
        int y0 = (int)floorf(yv);  y0 = min(max(y0, 0), HH - 2);
        s_x0[tid] = x0;  s_y0[tid] = y0;
        s_wx[tid] = xv - (float)x0;
        s_wy[tid] = yv - (float)y0;
        if (tid == 0) s_b = (int)__ldg(&rois[k * 5 + 0]);
    }
    __syncthreads();

    if (tid < 64) {
        int gy = tid >> 3, gx = tid & 7;
        float wy = s_wy[gy], wx = s_wx[gx];
        float sc = 0.25f * s_vy[gy] * s_vx[gx];
        s_w[gy][gx][0] = (1.0f - wy) * (1.0f - wx) * sc;
        s_w[gy][gx][1] = (1.0f - wy) * wx * sc;
        s_w[gy][gx][2] = wy * (1.0f - wx) * sc;
        s_w[gy][gx][3] = wy * wx * sc;
    }
    __syncthreads();

    // gather role: t4 = tap, col = 16B chunk within 1KB segment
    const int t4  = tid >> 6;
    const int dy  = t4 >> 1, dx = t4 & 1;
    const int col = tid & 63;
    const __half* bbase = FT + (size_t)s_b * (NPIX * CH) + chunk * 512
                             + (size_t)dx * CH + col * 8;
    int xoff[GPTS];
    #pragma unroll
    for (int gx = 0; gx < GPTS; gx++) xoff[gx] = s_x0[gx] * CH;

    const uint32_t tb0 = smem_u32(dynsmem);
    const uint32_t smy = tb0 + (t4 * 1024 + col * 16);

    #define GATHER(gy, bi)                                                  \
        do {                                                                \
            const __half* rb = bbase + (size_t)(s_y0[gy] + dy) * (WW * CH); \
            uint32_t sb = smy + (bi) * TB_BYTES;                            \
            _Pragma("unroll")                                               \
            for (int j = 0; j < 8; j++)                                     \
                CP_ASYNC16(sb + j * 4096, rb + xoff[j]);                    \
            cp_commit();                                                    \
        } while (0)

    GATHER(0, 0);                          // prologue: rows 0,1 in flight
    GATHER(1, 1);

    ull acc[49];
    #pragma unroll
    for (int i = 0; i < 49; i++) acc[i] = 0ULL;

    #pragma unroll
    for (int g = 0; g < GPTS; g++) {
        if (g < GPTS - 1) cp_wait<1>(); else cp_wait<0>();   // row g done
        __syncthreads();   // row-g taps visible; buf[(g+2)%3] free to refill
        if (g + 2 < GPTS) GATHER(g + 2, (g + 2) % 3);

        const unsigned char* buf = dynsmem + (g % 3) * TB_BYTES;
        ull rh[7];
        ull cprev = 0ULL;
        #pragma unroll
        for (int gx = 0; gx < GPTS; gx++) {
            const float4 w = *(const float4*)&s_w[g][gx][0];
            const unsigned char* sp = buf + (gx * 4) * 1024 + tid * 4;
            ull F00 = h2f2(*(const unsigned int*)(sp));
            ull F01 = h2f2(*(const unsigned int*)(sp + 1024));
            ull F10 = h2f2(*(const unsigned int*)(sp + 2048));
            ull F11 = h2f2(*(const unsigned int*)(sp + 3072));

            ull cur = fmul2(F00, dup2(w.x));
            cur = ffma2(F01, dup2(w.y), cur);
            cur = ffma2(F10, dup2(w.z), cur);
            cur = ffma2(F11, dup2(w.w), cur);

            if (gx > 0) rh[gx - 1] = fadd2(cprev, cur);
            cprev = cur;
        }
        // scatter rowsums into pooled rows g-1 and g
        #pragma unroll
        for (int px = 0; px < 7; px++) {
            if (g >= 1) acc[(g - 1) * 7 + px] = fadd2(acc[(g - 1) * 7 + px], rh[px]);
            if (g <  7) acc[ g      * 7 + px] = fadd2(acc[ g      * 7 + px], rh[px]);
        }
    }
    #undef GATHER

    // ---- staged, coalesced output writes (staging aliases buffer 0) ----
    float* sbuf = (float*)dynsmem;         // 25088 B < TB_BYTES
    float* outk = out + (size_t)k * (CH * 49) + (size_t)chunk * (512 * 49);
    #pragma unroll
    for (int sub = 0; sub < 4; sub++) {
        if ((tid >> 6) == sub) {
            int cl = tid * 2 - sub * 128;
            #pragma unroll
            for (int i = 0; i < 49; i++) {
                float2 v; memcpy(&v, &acc[i], 8);
                sbuf[(cl    ) * 49 + i] = v.x;
                sbuf[(cl + 1) * 49 + i] = v.y;
            }
        }
        __syncthreads();
        const float4* s4 = (const float4*)sbuf;
        float4* o4 = (float4*)(outk + sub * 6272);
        #pragma unroll
        for (int j = 0; j < 7; j++) {
            int i = tid + j * 256;
            if (i < 1568) o4[i] = s4[i];
        }
        __syncthreads();
    }
}

// ---------------------------------------------------------------------------
extern "C" void kernel_launch(void* const* d_in, const int* in_sizes, int n_in,
                              void* d_out, int out_size) {
    const float* features = (const float*)d_in[0];
    const float* rois     = (const float*)d_in[1];
    float* out            = (float*)d_out;

    const int smem = 3 * TB_BYTES;         // 96 KB
    static int done = 0;
    if (!done) {
        cudaFuncSetAttribute(roi_pool_kernel,
                             cudaFuncAttributeMaxDynamicSharedMemorySize, smem);
        done = 1;
    }

    dim3 tgrid((NPIX + 127) / 128, CH / 32, BB);   // (20, 32, 4)
    transpose_kernel<<<tgrid, 256>>>(features);
    roi_pool_kernel<<<dim3(KK, 2), 256, smem>>>(rois, out);
}